// round 16
// baseline (speedup 1.0000x reference)
#include <cuda_runtime.h>
#include <cuda_fp16.h>

// GuidedFilter, causal box window R=20 (trailing, clamped prefix at edges), H then W.
// Stage1: box{I,p,Ip,I2} -> A,b (fp16 half2 scratch).  Stage2: box{A,b} -> q.
//
// R16 = R15 (overlapped warp tiling: warp loads 128 cols, outputs 108; width-20
// window == shfl_up(prefix,5) from live lanes; fp16 scratch; __ldcs/__stcs)
// with __launch_bounds__(320, 3): regs<=68 allows 3 CTAs/SM, so all 384 CTAs
// are co-resident in ONE wave (R15's bounds-2 forced a 88-CTA straggler wave).

#define Hn 1024
#define Wn 1024
#define NIMG 24
#define R 20
#define NBAND 16
#define BANDH 64
#define TPB 320

// AB scratch: uint4 = 4 pixels x half2(A,b). 96 MB.
__device__ uint4 g_ABh[(size_t)NIMG * Hn * (Wn / 4)];

__device__ __forceinline__ unsigned int h2u(__half2 h) {
    return *reinterpret_cast<unsigned int*>(&h);
}
__device__ __forceinline__ void upk(unsigned int u, float& a, float& b) {
    __half2 h = *reinterpret_cast<__half2*>(&u);
    float2 f = __half22float2(h);
    a = f.x; b = f.y;
}

// Width-20 window, 4 elems/lane, subtrahend 5 lanes up. Valid for lane >= 5.
__device__ __forceinline__ void hwin(const float v[4], int lane, float w[4])
{
    const float p0 = v[0];
    const float p1 = __fadd_rn(p0, v[1]);
    const float p2 = __fadd_rn(p1, v[2]);
    const float p3 = __fadd_rn(p2, v[3]);
    const float T  = p3;

    const float t1 = __shfl_up_sync(0xffffffffu, T, 1);
    const float t2 = __shfl_up_sync(0xffffffffu, T, 2);
    const float t3 = __shfl_up_sync(0xffffffffu, T, 3);
    const float t4 = __shfl_up_sync(0xffffffffu, T, 4);
    const float t5 = __shfl_up_sync(0xffffffffu, T, 5);
    const float s0 = __shfl_up_sync(0xffffffffu, p0, 5);
    const float s1 = __shfl_up_sync(0xffffffffu, p1, 5);
    const float s2 = __shfl_up_sync(0xffffffffu, p2, 5);
    const float s3 = t5;                  // p3 == T

    float sumT = 0.0f;
    sumT = __fadd_rn(sumT, t1);           // lanes >= 5 always have 5 valid lanes above
    sumT = __fadd_rn(sumT, t2);
    sumT = __fadd_rn(sumT, t3);
    sumT = __fadd_rn(sumT, t4);
    sumT = __fadd_rn(sumT, t5);

    w[0] = __fsub_rn(__fadd_rn(p0, sumT), s0);
    w[1] = __fsub_rn(__fadd_rn(p1, sumT), s1);
    w[2] = __fsub_rn(__fadd_rn(p2, sumT), s2);
    w[3] = __fsub_rn(__fadd_rn(p3, sumT), s3);
}

__global__ void __launch_bounds__(TPB, 3)
gf_stage1(const float* __restrict__ gI, const float* __restrict__ gP)
{
    const int lane = threadIdx.x & 31;
    const int j    = threadIdx.x >> 5;        // warp 0..9
    const int band = blockIdx.x;
    const int img  = blockIdx.y;

    const int mi   = 27 * j - 5 + lane;       // float4 index of this lane's 4 cols
    const bool inc = (mi >= 0) && (mi < 256); // load guard
    const bool isOut = (lane >= 5) && (mi < 256);
    const int col0 = mi * 4;                  // first col (valid when isOut)
    const bool strip0 = (j == 0);

    const int r0 = band * BANDH;
    const int r1 = r0 + BANDH;
    const int gstart = (r0 >= R - 1) ? (r0 - (R - 1)) : 0;
    const int subStart = gstart + R;

    const float4* I4 = (const float4*)(gI + (size_t)img * Hn * Wn);
    const float4* P4 = (const float4*)(gP + (size_t)img * Hn * Wn);
    uint4* ABu = g_ABh + (size_t)img * Hn * (Wn / 4);

    float vI[4]  = {0,0,0,0}, vP[4]  = {0,0,0,0};
    float vIP[4] = {0,0,0,0}, vII[4] = {0,0,0,0};
    const float inv400 = 1.0f / 400.0f;
    const float4 zf4 = make_float4(0.f,0.f,0.f,0.f);

    for (int gi = gstart; gi < r1; ++gi) {
        const int rbase = gi << 8;
        float4 In = zf4, Pn = zf4, Io = zf4, Po = zf4;
        const bool doSub = (gi >= subStart);
        if (inc) {
            In = I4[rbase + mi];              // re-read as 'old' within 20 rows: keep in L2
            Pn = P4[rbase + mi];
            if (doSub) {
                const int obase = (gi - R) << 8;
                Io = __ldcs(I4 + obase + mi);
                Po = __ldcs(P4 + obase + mi);
            }
        }

        {
            const float in_[4] = {In.x, In.y, In.z, In.w};
            const float pn_[4] = {Pn.x, Pn.y, Pn.z, Pn.w};
            const float io_[4] = {Io.x, Io.y, Io.z, Io.w};
            const float po_[4] = {Po.x, Po.y, Po.z, Po.w};
            if (gi < R) {
                // exact sequential path (edge rows; ref-rounding bit-match)
#pragma unroll
                for (int e = 0; e < 4; ++e) {
                    vI[e]  = __fsub_rn(__fadd_rn(vI[e],  in_[e]), io_[e]);
                    vP[e]  = __fsub_rn(__fadd_rn(vP[e],  pn_[e]), po_[e]);
                    vIP[e] = __fsub_rn(__fadd_rn(vIP[e], __fmul_rn(in_[e], pn_[e])),
                                       __fmul_rn(io_[e], po_[e]));
                    vII[e] = __fsub_rn(__fadd_rn(vII[e], __fmul_rn(in_[e], in_[e])),
                                       __fmul_rn(io_[e], io_[e]));
                }
            } else {
#pragma unroll
                for (int e = 0; e < 4; ++e) {
                    vI[e]  = __fsub_rn(__fadd_rn(vI[e],  in_[e]), io_[e]);
                    vP[e]  = __fsub_rn(__fadd_rn(vP[e],  pn_[e]), po_[e]);
                    vIP[e] = fmaf(in_[e], pn_[e], fmaf(-io_[e], po_[e], vIP[e]));
                    vII[e] = fmaf(in_[e], in_[e], fmaf(-io_[e], io_[e], vII[e]));
                }
            }
        }

        if (gi >= r0) {
            float w0[4], w1[4], w2[4], w3[4];
            hwin(vI,  lane, w0);
            hwin(vP,  lane, w1);
            hwin(vIP, lane, w2);
            hwin(vII, lane, w3);

            if (isOut) {
                const bool divpath = (gi + 1 < R) || (strip0 && lane < 10);
                float A_[4], b_[4];
                if (divpath) {
                    const float Nrf = (gi + 1 < R) ? (float)(gi + 1) : 20.0f;
#pragma unroll
                    for (int e = 0; e < 4; ++e) {
                        const int colp1 = col0 + e + 1;
                        const float Ncf = (colp1 < R) ? (float)colp1 : 20.0f;
                        const float Nf = __fmul_rn(Nrf, Ncf);
                        const float m0 = __fdiv_rn(w0[e], Nf);
                        const float m1 = __fdiv_rn(w1[e], Nf);
                        const float m2 = __fdiv_rn(w2[e], Nf);
                        const float m3 = __fdiv_rn(w3[e], Nf);
                        const float cov = __fsub_rn(m2, __fmul_rn(m0, m1));
                        const float var = __fsub_rn(m3, __fmul_rn(m0, m0));
                        A_[e] = __fdiv_rn(cov, __fadd_rn(var, 1e-8f));
                        b_[e] = __fsub_rn(m1, __fmul_rn(A_[e], m0));
                    }
                } else {
#pragma unroll
                    for (int e = 0; e < 4; ++e) {
                        const float m0 = w0[e] * inv400;
                        const float m1 = w1[e] * inv400;
                        const float m2 = w2[e] * inv400;
                        const float m3 = w3[e] * inv400;
                        const float cov = fmaf(-m0, m1, m2);
                        const float var = fmaf(-m0, m0, m3);
                        const float A = __fdividef(cov, var + 1e-8f);
                        A_[e] = A;
                        b_[e] = fmaf(-A, m0, m1);
                    }
                }
                uint4 st;
                st.x = h2u(__floats2half2_rn(A_[0], b_[0]));
                st.y = h2u(__floats2half2_rn(A_[1], b_[1]));
                st.z = h2u(__floats2half2_rn(A_[2], b_[2]));
                st.w = h2u(__floats2half2_rn(A_[3], b_[3]));
                __stcs(ABu + rbase + mi, st);
            }
        }
    }
}

__global__ void __launch_bounds__(TPB, 3)
gf_stage2(const float* __restrict__ gI, float* __restrict__ gQ)
{
    const int lane = threadIdx.x & 31;
    const int j    = threadIdx.x >> 5;
    const int band = blockIdx.x;
    const int img  = blockIdx.y;

    const int mi   = 27 * j - 5 + lane;
    const bool inc = (mi >= 0) && (mi < 256);
    const bool isOut = (lane >= 5) && (mi < 256);
    const int col0 = mi * 4;
    const bool strip0 = (j == 0);

    const int r0 = band * BANDH;
    const int r1 = r0 + BANDH;
    const int gstart = (r0 >= R - 1) ? (r0 - (R - 1)) : 0;
    const int subStart = gstart + R;

    const float4* I4 = (const float4*)(gI + (size_t)img * Hn * Wn);
    const uint4* ABu = g_ABh + (size_t)img * Hn * (Wn / 4);
    float4* Q4 = (float4*)(gQ + (size_t)img * Hn * Wn);

    float vA[4] = {0,0,0,0}, vB[4] = {0,0,0,0};
    const float inv400 = 1.0f / 400.0f;
    const uint4 zu4 = make_uint4(0u,0u,0u,0u);    // half2(0,0)

    for (int gi = gstart; gi < r1; ++gi) {
        const int rbase = gi << 8;
        uint4 u = zu4, o = zu4;
        const bool doSub = (gi >= subStart);
        if (inc) {
            u = ABu[rbase + mi];              // re-read as 'old' within 20 rows: keep in L2
            if (doSub) o = __ldcs(ABu + ((gi - R) << 8) + mi);
        }

        {
            float an[4], bn[4], ao[4], bo[4];
            upk(u.x, an[0], bn[0]); upk(u.y, an[1], bn[1]);
            upk(u.z, an[2], bn[2]); upk(u.w, an[3], bn[3]);
            upk(o.x, ao[0], bo[0]); upk(o.y, ao[1], bo[1]);
            upk(o.z, ao[2], bo[2]); upk(o.w, ao[3], bo[3]);
#pragma unroll
            for (int e = 0; e < 4; ++e) {
                vA[e] = __fsub_rn(__fadd_rn(vA[e], an[e]), ao[e]);
                vB[e] = __fsub_rn(__fadd_rn(vB[e], bn[e]), bo[e]);
            }
        }

        if (gi >= r0) {
            float wA[4], wB[4];
            hwin(vA, lane, wA);
            hwin(vB, lane, wB);

            if (isOut) {
                const bool divpath = (gi + 1 < R) || (strip0 && lane < 10);
                const float4 Iv = __ldcs(I4 + rbase + mi);
                const float iv_[4] = {Iv.x, Iv.y, Iv.z, Iv.w};
                float q_[4];
                if (divpath) {
                    const float Nrf = (gi + 1 < R) ? (float)(gi + 1) : 20.0f;
#pragma unroll
                    for (int e = 0; e < 4; ++e) {
                        const int colp1 = col0 + e + 1;
                        const float Ncf = (colp1 < R) ? (float)colp1 : 20.0f;
                        const float Nf = __fmul_rn(Nrf, Ncf);
                        const float mA = __fdiv_rn(wA[e], Nf);
                        const float mB = __fdiv_rn(wB[e], Nf);
                        q_[e] = __fadd_rn(__fmul_rn(mA, iv_[e]), mB);
                    }
                } else {
#pragma unroll
                    for (int e = 0; e < 4; ++e) {
                        const float mA = wA[e] * inv400;
                        const float mB = wB[e] * inv400;
                        q_[e] = fmaf(mA, iv_[e], mB);
                    }
                }
                __stcs(Q4 + rbase + mi, make_float4(q_[0], q_[1], q_[2], q_[3]));
            }
        }
    }
}

extern "C" void kernel_launch(void* const* d_in, const int* in_sizes, int n_in,
                              void* d_out, int out_size)
{
    (void)in_sizes; (void)n_in; (void)out_size;
    const float* I = (const float*)d_in[0];
    const float* p = (const float*)d_in[1];
    float* q = (float*)d_out;

    dim3 grid(NBAND, NIMG);     // 10 warps per CTA cover all 1024 cols
    gf_stage1<<<grid, TPB>>>(I, p);
    gf_stage2<<<grid, TPB>>>(I, q);
}